// round 6
// baseline (speedup 1.0000x reference)
#include <cuda_runtime.h>
#include <cuda_bf16.h>
#include <math.h>
#include <stdint.h>

// Problem constants
constexpr int Bsz = 2;
constexpr int Tseq = 1024;
constexpr int Cdim = 1024;
constexpr int Hn   = 16;
constexpr int Ln   = 4;
constexpr int Vn   = 32000;
constexpr int NFF  = 4096;
constexpr int BT   = Bsz * Tseq;       // 2048 token rows

// Scratch (device globals; no allocation allowed)
__device__ float g_x  [BT * Cdim];          // residual stream
__device__ float g_nx [BT * Cdim];          // LN output
__device__ float g_qk [BT * 2 * Cdim];      // packed q,k projections
__device__ float g_y  [BT * Cdim];          // attention branch output
__device__ float g_pm [BT * Cdim];          // prefix-mean of nx
__device__ float g_ff [BT * NFF];           // MLP hidden
__device__ float g_cs [8 * Bsz * Cdim];     // chunk sums for prefix scan

// ---------------------------------------------------------------------------
// PTX helpers: tf32 convert (rna = unbiased), ldmatrix, mma
// ---------------------------------------------------------------------------
__device__ __forceinline__ float f2tf(float x) {
    uint32_t r;
    asm("cvt.rna.tf32.f32 %0, %1;" : "=r"(r) : "f"(x));
    return __uint_as_float(r);
}
__device__ __forceinline__ void ldsm4(uint32_t* r, const float* p) {
    uint32_t a = (uint32_t)__cvta_generic_to_shared(p);
    asm volatile("ldmatrix.sync.aligned.m8n8.x4.shared.b16 {%0,%1,%2,%3}, [%4];"
                 : "=r"(r[0]), "=r"(r[1]), "=r"(r[2]), "=r"(r[3]) : "r"(a));
}
__device__ __forceinline__ void mma8(float* c, const uint32_t* a, const uint32_t* b) {
    asm volatile(
        "mma.sync.aligned.m16n8k8.row.col.f32.tf32.tf32.f32 "
        "{%0,%1,%2,%3}, {%4,%5,%6,%7}, {%8,%9}, {%0,%1,%2,%3};"
        : "+f"(c[0]), "+f"(c[1]), "+f"(c[2]), "+f"(c[3])
        : "r"(a[0]), "r"(a[1]), "r"(a[2]), "r"(a[3]), "r"(b[0]), "r"(b[1]));
}

// ---------------------------------------------------------------------------
// Embedding
// ---------------------------------------------------------------------------
__global__ void __launch_bounds__(256)
embed_kernel(const int* __restrict__ ids, const float* __restrict__ wte,
             const float* __restrict__ wpe)
{
    int i = blockIdx.x * 256 + threadIdx.x;
    int base = i * 4;
    int bt = base >> 10;
    int c  = base & 1023;
    int t  = bt & 1023;
    int id = ids[bt];
    float4 a = *(const float4*)(wte + (size_t)id * Cdim + c);
    float4 p = *(const float4*)(wpe + (size_t)t  * Cdim + c);
    float4 o;
    o.x = a.x + p.x; o.y = a.y + p.y; o.z = a.z + p.z; o.w = a.w + p.w;
    *(float4*)(g_x + (size_t)bt * Cdim + c) = o;
}

// ---------------------------------------------------------------------------
// LayerNorm (bias=False, eps=1e-5)
// ---------------------------------------------------------------------------
__global__ void __launch_bounds__(256)
ln_kernel(const float* __restrict__ x, const float* __restrict__ w,
          float* __restrict__ out)
{
    __shared__ float red[8];
    __shared__ float stat[2];
    int row = blockIdx.x;
    int tid = threadIdx.x;
    const float* xr = x + (size_t)row * Cdim;
    float4 v = *(const float4*)(xr + tid * 4);

    float s = v.x + v.y + v.z + v.w;
    #pragma unroll
    for (int o = 16; o; o >>= 1) s += __shfl_xor_sync(0xffffffffu, s, o);
    if ((tid & 31) == 0) red[tid >> 5] = s;
    __syncthreads();
    if (tid < 8) {
        s = red[tid];
        #pragma unroll
        for (int o = 4; o; o >>= 1) s += __shfl_xor_sync(0xffu, s, o);
        if (tid == 0) stat[0] = s * (1.0f / Cdim);
    }
    __syncthreads();
    float mu = stat[0];
    float dx = v.x - mu, dy = v.y - mu, dz = v.z - mu, dw = v.w - mu;
    s = dx * dx + dy * dy + dz * dz + dw * dw;
    #pragma unroll
    for (int o = 16; o; o >>= 1) s += __shfl_xor_sync(0xffffffffu, s, o);
    if ((tid & 31) == 0) red[tid >> 5] = s;
    __syncthreads();
    if (tid < 8) {
        s = red[tid];
        #pragma unroll
        for (int o = 4; o; o >>= 1) s += __shfl_xor_sync(0xffu, s, o);
        if (tid == 0) stat[1] = rsqrtf(s * (1.0f / Cdim) + 1e-5f);
    }
    __syncthreads();
    float rstd = stat[1];
    float4 g = *(const float4*)(w + tid * 4);
    float4 o;
    o.x = dx * rstd * g.x; o.y = dy * rstd * g.y;
    o.z = dz * rstd * g.z; o.w = dw * rstd * g.w;
    *(float4*)(out + (size_t)row * Cdim + tid * 4) = o;
}

// ---------------------------------------------------------------------------
// Prefix-mean scan (row-major traversal: fully coalesced float4 rows)
// grid (16, 2): blockIdx.x = chunk*2 + b, blockIdx.y = channel half; 128 thr.
// ---------------------------------------------------------------------------
__global__ void __launch_bounds__(128)
pm_phase1(const float* __restrict__ nx)
{
    int chunk = blockIdx.x >> 1;
    int b = blockIdx.x & 1;
    int c = (blockIdx.y * 128 + threadIdx.x) * 4;
    const float* p = nx + (size_t)(b * Tseq + chunk * 128) * Cdim + c;
    float4 s = make_float4(0.f, 0.f, 0.f, 0.f);
    #pragma unroll 4
    for (int i = 0; i < 128; i++) {
        float4 v = *(const float4*)(p + (size_t)i * Cdim);
        s.x += v.x; s.y += v.y; s.z += v.z; s.w += v.w;
    }
    *(float4*)(g_cs + chunk * 2048 + b * 1024 + c) = s;
}

__global__ void __launch_bounds__(128)
pm_phase2(const float* __restrict__ nx, float* __restrict__ pm)
{
    int chunk = blockIdx.x >> 1;
    int b = blockIdx.x & 1;
    int c = (blockIdx.y * 128 + threadIdx.x) * 4;
    float4 s = make_float4(0.f, 0.f, 0.f, 0.f);
    for (int j = 0; j < chunk; j++) {
        float4 v = *(const float4*)(g_cs + j * 2048 + b * 1024 + c);
        s.x += v.x; s.y += v.y; s.z += v.z; s.w += v.w;
    }
    const float* p = nx + (size_t)(b * Tseq + chunk * 128) * Cdim + c;
    float* o = pm + (size_t)(b * Tseq + chunk * 128) * Cdim + c;
    #pragma unroll 4
    for (int i = 0; i < 128; i++) {
        float4 v = *(const float4*)(p + (size_t)i * Cdim);
        s.x += v.x; s.y += v.y; s.z += v.z; s.w += v.w;
        float inv = __fdividef(1.f, (float)(chunk * 128 + i + 1));
        float4 w;
        w.x = s.x * inv; w.y = s.y * inv; w.z = s.z * inv; w.w = s.w * inv;
        *(float4*)(o + (size_t)i * Cdim) = w;
    }
}

// ---------------------------------------------------------------------------
// tf32 tensor-core NT GEMM: C[M,N] = A[M,K] * B[N,K]^T (both row-major fp32)
// 128x128 block tile, BK=16, DOUBLE-BUFFERED smem (one barrier per K-tile),
// 8 warps, warp tile 32x64 (2 m16 x 8 n8 mma tiles).
// Data converted to tf32 (rna) at smem store; mma.sync.m16n8k8.tf32 compute.
// Epilogues: 0=store, 1=exact GELU, 2=residual combine out = rx + c1*ry + c2*acc
// Requires M%128==0, N%128==0, K%16==0 (true for all call sites).
// ---------------------------------------------------------------------------
#define GMODE_NONE 0
#define GMODE_GELU 1
#define GMODE_RES  2

__global__ void __launch_bounds__(256, 2)
gemm_nt_tf32(const float* __restrict__ A, const float* __restrict__ B,
             float* __restrict__ C, int M, int N, int K, int mode,
             const float* __restrict__ rx, const float* __restrict__ ry,
             const float* __restrict__ c1v, const float* __restrict__ c2v,
             int layer)
{
    // pitch 20 floats = 80B: 16B-aligned rows, 8-row ldmatrix groups hit all
    // 32 banks (20 mod 32 stepping tiles {0,4,8,...,28}).
    __shared__ float sA[2][128][20];
    __shared__ float sB[2][128][20];

    const int tid  = threadIdx.x;
    const int bm   = blockIdx.y * 128;
    const int bn   = blockIdx.x * 128;
    const int lane = tid & 31;
    const int warp = tid >> 5;
    const int wm   = warp >> 1;     // 0..3 : m offset wm*32
    const int wn   = warp & 1;      // 0..1 : n offset wn*64

    // gmem staging: 128 rows x 16 cols per matrix; each thread 2 rows x float4
    const int lrow = tid >> 2;          // 0..63
    const int lcol = (tid & 3) * 4;     // 0,4,8,12

    const float* Ag = A + (size_t)(bm + lrow) * K + lcol;
    const float* Bg = B + (size_t)(bn + lrow) * K + lcol;
    const size_t row64 = (size_t)64 * K;

    float4 ra0 = *(const float4*)(Ag);
    float4 ra1 = *(const float4*)(Ag + row64);
    float4 rb0 = *(const float4*)(Bg);
    float4 rb1 = *(const float4*)(Bg + row64);

    float acc[2][8][4];
    #pragma unroll
    for (int mi = 0; mi < 2; mi++)
        #pragma unroll
        for (int ni = 0; ni < 8; ni++)
            #pragma unroll
            for (int q = 0; q < 4; q++) acc[mi][ni][q] = 0.f;

    // ldmatrix per-lane source rows/cols (m8n8.x4 submatrix order)
    const int arow = (lane & 7) + ((lane >> 3) & 1) * 8;
    const int acol = (lane >> 4) * 4;
    const int brow = (lane & 7) + ((lane >> 4) & 1) * 8;
    const int bcol = ((lane >> 3) & 1) * 4;

    // stage 0 -> buffer 0
    {
        float* dA = &sA[0][lrow][lcol];
        dA[0] = f2tf(ra0.x); dA[1] = f2tf(ra0.y); dA[2] = f2tf(ra0.z); dA[3] = f2tf(ra0.w);
        float* dA2 = &sA[0][lrow + 64][lcol];
        dA2[0] = f2tf(ra1.x); dA2[1] = f2tf(ra1.y); dA2[2] = f2tf(ra1.z); dA2[3] = f2tf(ra1.w);
        float* dB = &sB[0][lrow][lcol];
        dB[0] = f2tf(rb0.x); dB[1] = f2tf(rb0.y); dB[2] = f2tf(rb0.z); dB[3] = f2tf(rb0.w);
        float* dB2 = &sB[0][lrow + 64][lcol];
        dB2[0] = f2tf(rb1.x); dB2[1] = f2tf(rb1.y); dB2[2] = f2tf(rb1.z); dB2[3] = f2tf(rb1.w);
    }
    __syncthreads();

    const int NT = K >> 4;
    for (int kt = 0; kt < NT; kt++) {
        const int cur = kt & 1;
        if (kt + 1 < NT) {
            int off = (kt + 1) << 4;
            ra0 = *(const float4*)(Ag + off);
            ra1 = *(const float4*)(Ag + off + row64);
            rb0 = *(const float4*)(Bg + off);
            rb1 = *(const float4*)(Bg + off + row64);
        }
        #pragma unroll
        for (int ks = 0; ks < 2; ks++) {
            uint32_t aF[2][4], bF[4][4];
            #pragma unroll
            for (int mi = 0; mi < 2; mi++)
                ldsm4(aF[mi], &sA[cur][wm * 32 + mi * 16 + arow][ks * 8 + acol]);
            #pragma unroll
            for (int nb = 0; nb < 4; nb++)
                ldsm4(bF[nb], &sB[cur][wn * 64 + nb * 16 + brow][ks * 8 + bcol]);
            #pragma unroll
            for (int mi = 0; mi < 2; mi++)
                #pragma unroll
                for (int ni = 0; ni < 8; ni++)
                    mma8(acc[mi][ni], aF[mi], &bF[ni >> 1][(ni & 1) * 2]);
        }
        if (kt + 1 < NT) {
            const int nxt = cur ^ 1;
            float* dA = &sA[nxt][lrow][lcol];
            dA[0] = f2tf(ra0.x); dA[1] = f2tf(ra0.y); dA[2] = f2tf(ra0.z); dA[3] = f2tf(ra0.w);
            float* dA2 = &sA[nxt][lrow + 64][lcol];
            dA2[0] = f2tf(ra1.x); dA2[1] = f2tf(ra1.y); dA2[2] = f2tf(ra1.z); dA2[3] = f2tf(ra1.w);
            float* dB = &sB[nxt][lrow][lcol];
            dB[0] = f2tf(rb0.x); dB[1] = f2tf(rb0.y); dB[2] = f2tf(rb0.z); dB[3] = f2tf(rb0.w);
            float* dB2 = &sB[nxt][lrow + 64][lcol];
            dB2[0] = f2tf(rb1.x); dB2[1] = f2tf(rb1.y); dB2[2] = f2tf(rb1.z); dB2[3] = f2tf(rb1.w);
            __syncthreads();
        }
    }

    float f1 = 0.f, f2 = 0.f;
    if (mode == GMODE_RES) { f1 = c1v[layer]; f2 = c2v[layer]; }
    const int gid = lane >> 2, tig = lane & 3;

    #pragma unroll
    for (int mi = 0; mi < 2; mi++) {
        #pragma unroll
        for (int ni = 0; ni < 8; ni++) {
            int col = bn + wn * 64 + ni * 8 + tig * 2;
            #pragma unroll
            for (int h = 0; h < 2; h++) {
                int row = bm + wm * 32 + mi * 16 + gid + h * 8;
                size_t off = (size_t)row * N + col;
                float v0 = acc[mi][ni][h * 2 + 0];
                float v1 = acc[mi][ni][h * 2 + 1];
                if (mode == GMODE_GELU) {
                    v0 = 0.5f * v0 * (1.f + erff(v0 * 0.70710678118654752f));
                    v1 = 0.5f * v1 * (1.f + erff(v1 * 0.70710678118654752f));
                } else if (mode == GMODE_RES) {
                    float2 x0 = *(const float2*)(rx + off);
                    float2 y0 = *(const float2*)(ry + off);
                    v0 = x0.x + f1 * y0.x + f2 * v0;
                    v1 = x0.y + f1 * y0.y + f2 * v1;
                }
                float2 o; o.x = v0; o.y = v1;
                *(float2*)(C + off) = o;
            }
        }
    }
}

// ---------------------------------------------------------------------------
// Fused causal attention + shaped-attention epilogue (fp32 SIMT).
//   y = beta * softmax(QK^T*scale) @ V + alpha * V_row - gamma * pm
// ---------------------------------------------------------------------------
__global__ void __launch_bounds__(256)
attn_kernel(const float* __restrict__ qkbuf, const float* __restrict__ nx,
            const float* __restrict__ pm, float* __restrict__ y,
            const float* __restrict__ al, const float* __restrict__ be,
            const float* __restrict__ ga, int layer)
{
    __shared__ float sQ[64][64];
    __shared__ float sKP[64][64];   // K transposed [d][c]; later P [r][c]
    __shared__ float sV[64][64];
    const int qt = blockIdx.x;
    const int bh = blockIdx.y;
    const int b = bh >> 4;
    const int h = bh & 15;
    const int tid = threadIdx.x;
    const int tx = tid & 15;
    const int ty = tid >> 4;
    const int q0 = qt * 64;
    const float scale = 0.125f;

    for (int i = tid; i < 64 * 16; i += 256) {
        int r = i >> 4, c4 = (i & 15) * 4;
        float4 v = *(const float4*)(qkbuf + (size_t)(b * Tseq + q0 + r) * (2 * Cdim)
                                    + h * 64 + c4);
        sQ[r][c4 + 0] = v.x * scale; sQ[r][c4 + 1] = v.y * scale;
        sQ[r][c4 + 2] = v.z * scale; sQ[r][c4 + 3] = v.w * scale;
    }

    float o[4][4];
    #pragma unroll
    for (int i = 0; i < 4; i++)
        #pragma unroll
        for (int j = 0; j < 4; j++) o[i][j] = 0.f;
    float mrow[4], lrow[4];
    #pragma unroll
    for (int i = 0; i < 4; i++) { mrow[i] = -INFINITY; lrow[i] = 0.f; }

    for (int jt = 0; jt <= qt; jt++) {
        int k0 = jt * 64;
        __syncthreads();
        for (int i = tid; i < 64 * 16; i += 256) {
            int r = i >> 4, c4 = (i & 15) * 4;
            float4 kv = *(const float4*)(qkbuf + (size_t)(b * Tseq + k0 + r) * (2 * Cdim)
                                         + Cdim + h * 64 + c4);
            sKP[c4 + 0][r] = kv.x; sKP[c4 + 1][r] = kv.y;
            sKP[c4 + 2][r] = kv.z; sKP[c4 + 3][r] = kv.w;
            float4 vv = *(const float4*)(nx + (size_t)(b * Tseq + k0 + r) * Cdim
                                         + h * 64 + c4);
            sV[r][c4 + 0] = vv.x; sV[r][c4 + 1] = vv.y;
            sV[r][c4 + 2] = vv.z; sV[r][c4 + 3] = vv.w;
        }
        __syncthreads();

        float s[4][4];
        #pragma unroll
        for (int i = 0; i < 4; i++)
            #pragma unroll
            for (int j = 0; j < 4; j++) s[i][j] = 0.f;
        #pragma unroll 8
        for (int d = 0; d < 64; d++) {
            float qv[4], kv[4];
            #pragma unroll
            for (int i = 0; i < 4; i++) qv[i] = sQ[ty * 4 + i][d];
            #pragma unroll
            for (int j = 0; j < 4; j++) kv[j] = sKP[d][tx + 16 * j];
            #pragma unroll
            for (int i = 0; i < 4; i++)
                #pragma unroll
                for (int j = 0; j < 4; j++)
                    s[i][j] = fmaf(qv[i], kv[j], s[i][j]);
        }
        if (jt == qt) {
            #pragma unroll
            for (int i = 0; i < 4; i++)
                #pragma unroll
                for (int j = 0; j < 4; j++)
                    if (tx + 16 * j > ty * 4 + i) s[i][j] = -INFINITY;
        }

        float corr[4];
        #pragma unroll
        for (int i = 0; i < 4; i++) {
            float mt = fmaxf(fmaxf(s[i][0], s[i][1]), fmaxf(s[i][2], s[i][3]));
            #pragma unroll
            for (int off = 8; off; off >>= 1)
                mt = fmaxf(mt, __shfl_xor_sync(0xffffffffu, mt, off, 16));
            float mnew = fmaxf(mrow[i], mt);
            corr[i] = __expf(mrow[i] - mnew);
            mrow[i] = mnew;
            float sum = 0.f;
            #pragma unroll
            for (int j = 0; j < 4; j++) {
                s[i][j] = __expf(s[i][j] - mnew);
                sum += s[i][j];
            }
            #pragma unroll
            for (int off = 8; off; off >>= 1)
                sum += __shfl_xor_sync(0xffffffffu, sum, off, 16);
            lrow[i] = lrow[i] * corr[i] + sum;
        }

        __syncthreads();
        #pragma unroll
        for (int i = 0; i < 4; i++)
            #pragma unroll
            for (int j = 0; j < 4; j++)
                sKP[ty * 4 + i][tx + 16 * j] = s[i][j];
        __syncthreads();

        #pragma unroll
        for (int i = 0; i < 4; i++)
            #pragma unroll
            for (int j = 0; j < 4; j++) o[i][j] *= corr[i];
        #pragma unroll 8
        for (int k = 0; k < 64; k++) {
            float pv[4], vv[4];
            #pragma unroll
            for (int i = 0; i < 4; i++) pv[i] = sKP[ty * 4 + i][k];
            #pragma unroll
            for (int j = 0; j < 4; j++) vv[j] = sV[k][tx + 16 * j];
            #pragma unroll
            for (int i = 0; i < 4; i++)
                #pragma unroll
                for (int j = 0; j < 4; j++)
                    o[i][j] = fmaf(pv[i], vv[j], o[i][j]);
        }
    }

    float alpha = al[layer], beta = be[layer], gamma = ga[layer];
    #pragma unroll
    for (int i = 0; i < 4; i++) {
        int r = q0 + ty * 4 + i;
        size_t base = (size_t)(b * Tseq + r) * Cdim + h * 64;
        float inv = __fdividef(1.f, lrow[i]);
        #pragma unroll
        for (int j = 0; j < 4; j++) {
            int c = tx + 16 * j;
            y[base + c] = beta * o[i][j] * inv + alpha * nx[base + c]
                          - gamma * pm[base + c];
        }
    }
}

// ---------------------------------------------------------------------------
// Host orchestration
// ---------------------------------------------------------------------------
extern "C" void kernel_launch(void* const* d_in, const int* in_sizes, int n_in,
                              void* d_out, int out_size)
{
    (void)in_sizes; (void)n_in; (void)out_size;
    const int*   ids   = (const int*)  d_in[0];
    const float* wte   = (const float*)d_in[1];
    const float* wpe   = (const float*)d_in[2];
    const float* Wattn = (const float*)d_in[3];
    const float* Wfc   = (const float*)d_in[4];
    const float* Wproj = (const float*)d_in[5];
    const float* ln_w  = (const float*)d_in[6];
    const float* alpha = (const float*)d_in[7];
    const float* beta  = (const float*)d_in[8];
    const float* gamma = (const float*)d_in[9];
    const float* bSA   = (const float*)d_in[10];
    const float* bFF   = (const float*)d_in[11];
    const float* lnf_w = (const float*)d_in[12];
    float* out = (float*)d_out;

    float *x, *nx, *qk, *y, *pm, *ff;
    cudaGetSymbolAddress((void**)&x,  g_x);
    cudaGetSymbolAddress((void**)&nx, g_nx);
    cudaGetSymbolAddress((void**)&qk, g_qk);
    cudaGetSymbolAddress((void**)&y,  g_y);
    cudaGetSymbolAddress((void**)&pm, g_pm);
    cudaGetSymbolAddress((void**)&ff, g_ff);

    embed_kernel<<<BT * Cdim / 4 / 256, 256>>>(ids, wte, wpe);

    for (int i = 0; i < Ln; i++) {
        ln_kernel<<<BT, 256>>>(x, ln_w + (size_t)i * Cdim, nx);
        pm_phase1<<<dim3(16, 2), 128>>>(nx);
        pm_phase2<<<dim3(16, 2), 128>>>(nx, pm);
        // qk = nx @ Wattn[i]^T : [BT, 2C]
        gemm_nt_tf32<<<dim3(2 * Cdim / 128, BT / 128), 256>>>(
            nx, Wattn + (size_t)i * 2 * Cdim * Cdim, qk,
            BT, 2 * Cdim, Cdim, GMODE_NONE, nullptr, nullptr, nullptr, nullptr, 0);
        // attention branch -> y
        attn_kernel<<<dim3(Tseq / 64, Bsz * Hn), 256>>>(
            qk, nx, pm, y, alpha, beta, gamma, i);
        // h = gelu(nx @ Wfc[i]^T) : [BT, NFF]
        gemm_nt_tf32<<<dim3(NFF / 128, BT / 128), 256>>>(
            nx, Wfc + (size_t)i * NFF * Cdim, ff,
            BT, NFF, Cdim, GMODE_GELU, nullptr, nullptr, nullptr, nullptr, 0);
        // x = x + bSA*y + bFF*(h @ Wproj[i]^T)
        gemm_nt_tf32<<<dim3(Cdim / 128, BT / 128), 256>>>(
            ff, Wproj + (size_t)i * Cdim * NFF, x,
            BT, Cdim, NFF, GMODE_RES, x, y, bSA, bFF, i);
    }

    ln_kernel<<<BT, 256>>>(x, lnf_w, nx);
    // logits = nx @ wte^T : [BT, V]
    gemm_nt_tf32<<<dim3(Vn / 128, BT / 128), 256>>>(
        nx, wte, out, BT, Vn, Cdim, GMODE_NONE,
        nullptr, nullptr, nullptr, nullptr, 0);
}

// round 8
// speedup vs baseline: 1.0742x; 1.0742x over previous
#include <cuda_runtime.h>
#include <cuda_bf16.h>
#include <math.h>
#include <stdint.h>

// Problem constants
constexpr int Bsz = 2;
constexpr int Tseq = 1024;
constexpr int Cdim = 1024;
constexpr int Hn   = 16;
constexpr int Ln   = 4;
constexpr int Vn   = 32000;
constexpr int NFF  = 4096;
constexpr int BT   = Bsz * Tseq;       // 2048 token rows

// Scratch (device globals; no allocation allowed)
__device__ float g_x  [BT * Cdim];          // residual stream
__device__ float g_nx [BT * Cdim];          // LN output
__device__ float g_qk [BT * 2 * Cdim];      // packed q,k projections
__device__ float g_y  [BT * Cdim];          // attention branch output
__device__ float g_pm [BT * Cdim];          // prefix-mean of nx
__device__ float g_ff [BT * NFF];           // MLP hidden
__device__ float g_cs [8 * Bsz * Cdim];     // chunk sums for prefix scan

// ---------------------------------------------------------------------------
// PTX helpers: tf32 convert (rna = unbiased), ldmatrix, mma
// ---------------------------------------------------------------------------
__device__ __forceinline__ float f2tf(float x) {
    uint32_t r;
    asm("cvt.rna.tf32.f32 %0, %1;" : "=r"(r) : "f"(x));
    return __uint_as_float(r);
}
__device__ __forceinline__ void ldsm4(uint32_t* r, const float* p) {
    uint32_t a = (uint32_t)__cvta_generic_to_shared(p);
    asm volatile("ldmatrix.sync.aligned.m8n8.x4.shared.b16 {%0,%1,%2,%3}, [%4];"
                 : "=r"(r[0]), "=r"(r[1]), "=r"(r[2]), "=r"(r[3]) : "r"(a));
}
__device__ __forceinline__ void mma8(float* c, const uint32_t* a, const uint32_t* b) {
    asm volatile(
        "mma.sync.aligned.m16n8k8.row.col.f32.tf32.tf32.f32 "
        "{%0,%1,%2,%3}, {%4,%5,%6,%7}, {%8,%9}, {%0,%1,%2,%3};"
        : "+f"(c[0]), "+f"(c[1]), "+f"(c[2]), "+f"(c[3])
        : "r"(a[0]), "r"(a[1]), "r"(a[2]), "r"(a[3]), "r"(b[0]), "r"(b[1]));
}

// ---------------------------------------------------------------------------
// Embedding
// ---------------------------------------------------------------------------
__global__ void __launch_bounds__(256)
embed_kernel(const int* __restrict__ ids, const float* __restrict__ wte,
             const float* __restrict__ wpe)
{
    int i = blockIdx.x * 256 + threadIdx.x;
    int base = i * 4;
    int bt = base >> 10;
    int c  = base & 1023;
    int t  = bt & 1023;
    int id = ids[bt];
    float4 a = *(const float4*)(wte + (size_t)id * Cdim + c);
    float4 p = *(const float4*)(wpe + (size_t)t  * Cdim + c);
    float4 o;
    o.x = a.x + p.x; o.y = a.y + p.y; o.z = a.z + p.z; o.w = a.w + p.w;
    *(float4*)(g_x + (size_t)bt * Cdim + c) = o;
}

// ---------------------------------------------------------------------------
// LayerNorm (bias=False, eps=1e-5)
// ---------------------------------------------------------------------------
__global__ void __launch_bounds__(256)
ln_kernel(const float* __restrict__ x, const float* __restrict__ w,
          float* __restrict__ out)
{
    __shared__ float red[8];
    __shared__ float stat[2];
    int row = blockIdx.x;
    int tid = threadIdx.x;
    const float* xr = x + (size_t)row * Cdim;
    float4 v = *(const float4*)(xr + tid * 4);

    float s = v.x + v.y + v.z + v.w;
    #pragma unroll
    for (int o = 16; o; o >>= 1) s += __shfl_xor_sync(0xffffffffu, s, o);
    if ((tid & 31) == 0) red[tid >> 5] = s;
    __syncthreads();
    if (tid < 8) {
        s = red[tid];
        #pragma unroll
        for (int o = 4; o; o >>= 1) s += __shfl_xor_sync(0xffu, s, o);
        if (tid == 0) stat[0] = s * (1.0f / Cdim);
    }
    __syncthreads();
    float mu = stat[0];
    float dx = v.x - mu, dy = v.y - mu, dz = v.z - mu, dw = v.w - mu;
    s = dx * dx + dy * dy + dz * dz + dw * dw;
    #pragma unroll
    for (int o = 16; o; o >>= 1) s += __shfl_xor_sync(0xffffffffu, s, o);
    if ((tid & 31) == 0) red[tid >> 5] = s;
    __syncthreads();
    if (tid < 8) {
        s = red[tid];
        #pragma unroll
        for (int o = 4; o; o >>= 1) s += __shfl_xor_sync(0xffu, s, o);
        if (tid == 0) stat[1] = rsqrtf(s * (1.0f / Cdim) + 1e-5f);
    }
    __syncthreads();
    float rstd = stat[1];
    float4 g = *(const float4*)(w + tid * 4);
    float4 o;
    o.x = dx * rstd * g.x; o.y = dy * rstd * g.y;
    o.z = dz * rstd * g.z; o.w = dw * rstd * g.w;
    *(float4*)(out + (size_t)row * Cdim + tid * 4) = o;
}

// ---------------------------------------------------------------------------
// Prefix-mean scan (R5 column version: high thread count hides latency)
// ---------------------------------------------------------------------------
__global__ void __launch_bounds__(256)
pm_phase1(const float* __restrict__ nx)
{
    int g = blockIdx.x * 256 + threadIdx.x;       // 8 * B * C = 16384
    int chunk = g >> 11;
    int bc = g & 2047;
    int b = bc >> 10, c = bc & 1023;
    const float* p = nx + (size_t)(b * Tseq + chunk * 128) * Cdim + c;
    float s = 0.f;
    #pragma unroll 8
    for (int i = 0; i < 128; i++) s += p[(size_t)i * Cdim];
    g_cs[g] = s;
}

__global__ void __launch_bounds__(256)
pm_phase2(const float* __restrict__ nx, float* __restrict__ pm)
{
    int g = blockIdx.x * 256 + threadIdx.x;
    int chunk = g >> 11;
    int bc = g & 2047;
    int b = bc >> 10, c = bc & 1023;
    float s = 0.f;
    for (int j = 0; j < chunk; j++) s += g_cs[j * 2048 + bc];
    const float* p = nx + (size_t)(b * Tseq + chunk * 128) * Cdim + c;
    float* o = pm + (size_t)(b * Tseq + chunk * 128) * Cdim + c;
    #pragma unroll 4
    for (int i = 0; i < 128; i++) {
        s += p[(size_t)i * Cdim];
        o[(size_t)i * Cdim] = __fdividef(s, (float)(chunk * 128 + i + 1));
    }
}

// ---------------------------------------------------------------------------
// tf32 tensor-core NT GEMM (R5 version): C[M,N] = A[M,K] * B[N,K]^T
// 128x128 block tile, BK=32, single-buffered, 8 warps, warp tile 32x64.
// ---------------------------------------------------------------------------
#define GMODE_NONE 0
#define GMODE_GELU 1
#define GMODE_RES  2

__global__ void __launch_bounds__(256, 2)
gemm_nt_tf32(const float* __restrict__ A, const float* __restrict__ B,
             float* __restrict__ C, int M, int N, int K, int mode,
             const float* __restrict__ rx, const float* __restrict__ ry,
             const float* __restrict__ c1v, const float* __restrict__ c2v,
             int layer)
{
    __shared__ float sA[128][36];   // [m][k], +4 pad keeps ldmatrix rows conflict-free
    __shared__ float sB[128][36];   // [n][k]

    const int tid  = threadIdx.x;
    const int bm   = blockIdx.y * 128;
    const int bn   = blockIdx.x * 128;
    const int lane = tid & 31;
    const int warp = tid >> 5;
    const int wm   = warp >> 1;     // 0..3 : m offset wm*32
    const int wn   = warp & 1;      // 0..1 : n offset wn*64

    const int lrow = tid >> 3;          // 0..31
    const int lcol = (tid & 7) * 4;     // 0..28

    const float* Ag = A + (size_t)(bm + lrow) * K + lcol;
    const float* Bg = B + (size_t)(bn + lrow) * K + lcol;

    float4 ra[4], rb[4];
    #pragma unroll
    for (int i = 0; i < 4; i++) {
        ra[i] = *(const float4*)(Ag + (size_t)(32 * i) * K);
        rb[i] = *(const float4*)(Bg + (size_t)(32 * i) * K);
    }

    float acc[2][8][4];
    #pragma unroll
    for (int mi = 0; mi < 2; mi++)
        #pragma unroll
        for (int ni = 0; ni < 8; ni++)
            #pragma unroll
            for (int q = 0; q < 4; q++) acc[mi][ni][q] = 0.f;

    const int arow = (lane & 7) + ((lane >> 3) & 1) * 8;
    const int acol = (lane >> 4) * 4;
    const int brow = (lane & 7) + ((lane >> 4) & 1) * 8;
    const int bcol = ((lane >> 3) & 1) * 4;

    for (int k0 = 0; k0 < K; k0 += 32) {
        __syncthreads();
        #pragma unroll
        for (int i = 0; i < 4; i++) {
            float* dA = &sA[lrow + 32 * i][lcol];
            dA[0] = f2tf(ra[i].x); dA[1] = f2tf(ra[i].y);
            dA[2] = f2tf(ra[i].z); dA[3] = f2tf(ra[i].w);
            float* dB = &sB[lrow + 32 * i][lcol];
            dB[0] = f2tf(rb[i].x); dB[1] = f2tf(rb[i].y);
            dB[2] = f2tf(rb[i].z); dB[3] = f2tf(rb[i].w);
        }
        __syncthreads();
        if (k0 + 32 < K) {
            #pragma unroll
            for (int i = 0; i < 4; i++) {
                ra[i] = *(const float4*)(Ag + (size_t)(32 * i) * K + k0 + 32);
                rb[i] = *(const float4*)(Bg + (size_t)(32 * i) * K + k0 + 32);
            }
        }
        #pragma unroll
        for (int ks = 0; ks < 4; ks++) {
            uint32_t aF[2][4], bF[4][4];
            #pragma unroll
            for (int mi = 0; mi < 2; mi++)
                ldsm4(aF[mi], &sA[wm * 32 + mi * 16 + arow][ks * 8 + acol]);
            #pragma unroll
            for (int nb = 0; nb < 4; nb++)
                ldsm4(bF[nb], &sB[wn * 64 + nb * 16 + brow][ks * 8 + bcol]);
            #pragma unroll
            for (int mi = 0; mi < 2; mi++)
                #pragma unroll
                for (int ni = 0; ni < 8; ni++)
                    mma8(acc[mi][ni], aF[mi], &bF[ni >> 1][(ni & 1) * 2]);
        }
    }

    float f1 = 0.f, f2 = 0.f;
    if (mode == GMODE_RES) { f1 = c1v[layer]; f2 = c2v[layer]; }
    const int gid = lane >> 2, tig = lane & 3;

    #pragma unroll
    for (int mi = 0; mi < 2; mi++) {
        #pragma unroll
        for (int ni = 0; ni < 8; ni++) {
            int col = bn + wn * 64 + ni * 8 + tig * 2;
            #pragma unroll
            for (int h = 0; h < 2; h++) {
                int row = bm + wm * 32 + mi * 16 + gid + h * 8;
                size_t off = (size_t)row * N + col;
                float v0 = acc[mi][ni][h * 2 + 0];
                float v1 = acc[mi][ni][h * 2 + 1];
                if (mode == GMODE_GELU) {
                    v0 = 0.5f * v0 * (1.f + erff(v0 * 0.70710678118654752f));
                    v1 = 0.5f * v1 * (1.f + erff(v1 * 0.70710678118654752f));
                } else if (mode == GMODE_RES) {
                    float2 x0 = *(const float2*)(rx + off);
                    float2 y0 = *(const float2*)(ry + off);
                    v0 = x0.x + f1 * y0.x + f2 * v0;
                    v1 = x0.y + f1 * y0.y + f2 * v1;
                }
                float2 o; o.x = v0; o.y = v1;
                *(float2*)(C + off) = o;
            }
        }
    }
}

// ---------------------------------------------------------------------------
// Fused causal attention + shaped-attention epilogue (fp32 SIMT, vectorized).
//   y = beta * softmax(QK^T*scale) @ V + alpha * V_row - gamma * pm
// Inner loops chunked by 4 along d/k with explicit float4 loads for the
// broadcast operands (sQ rows, P rows); K/V reads stay scalar conflict-free.
// ---------------------------------------------------------------------------
__global__ void __launch_bounds__(256)
attn_kernel(const float* __restrict__ qkbuf, const float* __restrict__ nx,
            const float* __restrict__ pm, float* __restrict__ y,
            const float* __restrict__ al, const float* __restrict__ be,
            const float* __restrict__ ga, int layer)
{
    __shared__ float sQ[64][64];    // [r][d]
    __shared__ float sKP[64][64];   // K transposed [d][c]; later P [r][c]
    __shared__ float sV[64][64];    // [k][c]
    const int qt = blockIdx.x;
    const int bh = blockIdx.y;
    const int b = bh >> 4;
    const int h = bh & 15;
    const int tid = threadIdx.x;
    const int tx = tid & 15;
    const int ty = tid >> 4;
    const int q0 = qt * 64;
    const float scale = 0.125f;

    for (int i = tid; i < 64 * 16; i += 256) {
        int r = i >> 4, c4 = (i & 15) * 4;
        float4 v = *(const float4*)(qkbuf + (size_t)(b * Tseq + q0 + r) * (2 * Cdim)
                                    + h * 64 + c4);
        sQ[r][c4 + 0] = v.x * scale; sQ[r][c4 + 1] = v.y * scale;
        sQ[r][c4 + 2] = v.z * scale; sQ[r][c4 + 3] = v.w * scale;
    }

    float o[4][4];
    #pragma unroll
    for (int i = 0; i < 4; i++)
        #pragma unroll
        for (int j = 0; j < 4; j++) o[i][j] = 0.f;
    float mrow[4], lrow[4];
    #pragma unroll
    for (int i = 0; i < 4; i++) { mrow[i] = -INFINITY; lrow[i] = 0.f; }

    for (int jt = 0; jt <= qt; jt++) {
        int k0 = jt * 64;
        __syncthreads();
        for (int i = tid; i < 64 * 16; i += 256) {
            int r = i >> 4, c4 = (i & 15) * 4;
            float4 kv = *(const float4*)(qkbuf + (size_t)(b * Tseq + k0 + r) * (2 * Cdim)
                                         + Cdim + h * 64 + c4);
            sKP[c4 + 0][r] = kv.x; sKP[c4 + 1][r] = kv.y;
            sKP[c4 + 2][r] = kv.z; sKP[c4 + 3][r] = kv.w;
            float4 vv = *(const float4*)(nx + (size_t)(b * Tseq + k0 + r) * Cdim
                                         + h * 64 + c4);
            sV[r][c4 + 0] = vv.x; sV[r][c4 + 1] = vv.y;
            sV[r][c4 + 2] = vv.z; sV[r][c4 + 3] = vv.w;
        }
        __syncthreads();

        // S fragment: rows r = ty*4+i, cols c = tx + 16*j
        float s[4][4];
        #pragma unroll
        for (int i = 0; i < 4; i++)
            #pragma unroll
            for (int j = 0; j < 4; j++) s[i][j] = 0.f;
        #pragma unroll 4
        for (int d0 = 0; d0 < 64; d0 += 4) {
            float4 qv[4];
            #pragma unroll
            for (int i = 0; i < 4; i++)
                qv[i] = *(const float4*)&sQ[ty * 4 + i][d0];
            float kv[4][4];   // [dd][j]
            #pragma unroll
            for (int dd = 0; dd < 4; dd++)
                #pragma unroll
                for (int j = 0; j < 4; j++)
                    kv[dd][j] = sKP[d0 + dd][tx + 16 * j];
            #pragma unroll
            for (int i = 0; i < 4; i++)
                #pragma unroll
                for (int j = 0; j < 4; j++) {
                    s[i][j] = fmaf(qv[i].x, kv[0][j], s[i][j]);
                    s[i][j] = fmaf(qv[i].y, kv[1][j], s[i][j]);
                    s[i][j] = fmaf(qv[i].z, kv[2][j], s[i][j]);
                    s[i][j] = fmaf(qv[i].w, kv[3][j], s[i][j]);
                }
        }
        if (jt == qt) {
            #pragma unroll
            for (int i = 0; i < 4; i++)
                #pragma unroll
                for (int j = 0; j < 4; j++)
                    if (tx + 16 * j > ty * 4 + i) s[i][j] = -INFINITY;
        }

        float corr[4];
        #pragma unroll
        for (int i = 0; i < 4; i++) {
            float mt = fmaxf(fmaxf(s[i][0], s[i][1]), fmaxf(s[i][2], s[i][3]));
            #pragma unroll
            for (int off = 8; off; off >>= 1)
                mt = fmaxf(mt, __shfl_xor_sync(0xffffffffu, mt, off, 16));
            float mnew = fmaxf(mrow[i], mt);
            corr[i] = __expf(mrow[i] - mnew);
            mrow[i] = mnew;
            float sum = 0.f;
            #pragma unroll
            for (int j = 0; j < 4; j++) {
                s[i][j] = __expf(s[i][j] - mnew);
                sum += s[i][j];
            }
            #pragma unroll
            for (int off = 8; off; off >>= 1)
                sum += __shfl_xor_sync(0xffffffffu, sum, off, 16);
            lrow[i] = lrow[i] * corr[i] + sum;
        }

        __syncthreads();   // everyone done reading K from sKP
        #pragma unroll
        for (int i = 0; i < 4; i++)
            #pragma unroll
            for (int j = 0; j < 4; j++)
                sKP[ty * 4 + i][tx + 16 * j] = s[i][j];   // P, row-major
        __syncthreads();

        #pragma unroll
        for (int i = 0; i < 4; i++)
            #pragma unroll
            for (int j = 0; j < 4; j++) o[i][j] *= corr[i];
        #pragma unroll 4
        for (int k0c = 0; k0c < 64; k0c += 4) {
            float4 pv[4];
            #pragma unroll
            for (int i = 0; i < 4; i++)
                pv[i] = *(const float4*)&sKP[ty * 4 + i][k0c];
            float vv[4][4];   // [kk][j]
            #pragma unroll
            for (int kk = 0; kk < 4; kk++)
                #pragma unroll
                for (int j = 0; j < 4; j++)
                    vv[kk][j] = sV[k0c + kk][tx + 16 * j];
            #pragma unroll
            for (int i = 0; i < 4; i++)
                #pragma unroll
                for (int j = 0; j < 4; j++) {
                    o[i][j] = fmaf(pv[i].x, vv[0][j], o[i][j]);
                    o[i][j] = fmaf(pv[i].y, vv[1][j], o[i][j]);
                    o[i][j] = fmaf(pv[i].z, vv[2][j], o[i][j]);
                    o[i][j] = fmaf(pv[i].w, vv[3][j], o[i][j]);
                }
        }
    }

    float alpha = al[layer], beta = be[layer], gamma = ga[layer];
    #pragma unroll
    for (int i = 0; i < 4; i++) {
        int r = q0 + ty * 4 + i;
        size_t base = (size_t)(b * Tseq + r) * Cdim + h * 64;
        float inv = __fdividef(1.f, lrow[i]);
        #pragma unroll
        for (int j = 0; j < 4; j++) {
            int c = tx + 16 * j;
            y[base + c] = beta * o[i][j] * inv + alpha * nx[base + c]
                          - gamma * pm[base + c];
        }
    }
}

// ---------------------------------------------------------------------------
// Host orchestration
// ---------------------------------------------------------------------------
extern "C" void kernel_launch(void* const* d_in, const int* in_sizes, int n_in,
                              void* d_out, int out_size)
{
    (void)in_sizes; (void)n_in; (void)out_size;
    const int*   ids   = (const int*)  d_in[0];
    const float* wte   = (const float*)d_in[1];
    const float* wpe   = (const float*)d_in[2];
    const float* Wattn = (const float*)d_in[3];
    const float* Wfc   = (const float*)d_in[4];
    const float* Wproj = (const float*)d_in[5];
    const float* ln_w  = (const float*)d_in[6];
    const float* alpha = (const float*)d_in[7];
    const float* beta  = (const float*)d_in[8];
    const float* gamma = (const float*)d_in[9];
    const float* bSA   = (const float*)d_in[10];
    const float* bFF   = (const float*)d_in[11];
    const float* lnf_w = (const float*)d_in[12];
    float* out = (float*)d_out;

    float *x, *nx, *qk, *y, *pm, *ff;
    cudaGetSymbolAddress((void**)&x,  g_x);
    cudaGetSymbolAddress((void**)&nx, g_nx);
    cudaGetSymbolAddress((void**)&qk, g_qk);
    cudaGetSymbolAddress((void**)&y,  g_y);
    cudaGetSymbolAddress((void**)&pm, g_pm);
    cudaGetSymbolAddress((void**)&ff, g_ff);

    embed_kernel<<<BT * Cdim / 4 / 256, 256>>>(ids, wte, wpe);

    for (int i = 0; i < Ln; i++) {
        ln_kernel<<<BT, 256>>>(x, ln_w + (size_t)i * Cdim, nx);
        pm_phase1<<<64, 256>>>(nx);
        pm_phase2<<<64, 256>>>(nx, pm);
        // qk = nx @ Wattn[i]^T : [BT, 2C]
        gemm_nt_tf32<<<dim3(2 * Cdim / 128, BT / 128), 256>>>(
            nx, Wattn + (size_t)i * 2 * Cdim * Cdim, qk,
            BT, 2 * Cdim, Cdim, GMODE_NONE, nullptr, nullptr, nullptr, nullptr, 0);
        // attention branch -> y
        attn_kernel<<<dim3(Tseq / 64, Bsz * Hn), 256>>>(
            qk, nx, pm, y, alpha, beta, gamma, i);
        // h = gelu(nx @ Wfc[i]^T) : [BT, NFF]
        gemm_nt_tf32<<<dim3(NFF / 128, BT / 128), 256>>>(
            nx, Wfc + (size_t)i * NFF * Cdim, ff,
            BT, NFF, Cdim, GMODE_GELU, nullptr, nullptr, nullptr, nullptr, 0);
        // x = x + bSA*y + bFF*(h @ Wproj[i]^T)
        gemm_nt_tf32<<<dim3(Cdim / 128, BT / 128), 256>>>(
            ff, Wproj + (size_t)i * Cdim * NFF, x,
            BT, Cdim, NFF, GMODE_RES, x, y, bSA, bFF, i);
    }

    ln_kernel<<<BT, 256>>>(x, lnf_w, nx);
    // logits = nx @ wte^T : [BT, V]
    gemm_nt_tf32<<<dim3(Vn / 128, BT / 128), 256>>>(
        nx, wte, out, BT, Vn, Cdim, GMODE_NONE,
        nullptr, nullptr, nullptr, nullptr, 0);
}